// round 3
// baseline (speedup 1.0000x reference)
#include <cuda_runtime.h>
#include <math.h>

// ---------------------------------------------------------------------------
// Problem constants
// ---------------------------------------------------------------------------
#define BATCH 512
#define MF    48      // fields
#define DD    128     // embedding dim
#define O1    68
#define O2    32
#define O3    24
#define K1TRI 1176    // 48*49/2 symmetric pairs for layer 1
#define K2    (O1*MF) // 3264
#define KT    32      // k-tile

// ---------------------------------------------------------------------------
// Device-global scratch (no allocation allowed)
// ---------------------------------------------------------------------------
__device__ float         g_wsym[K1TRI * O1];   // symmetrized w_cin1
__device__ unsigned char g_pk[K1TRI], g_pj[K1TRI];
__device__ float         g_V3[O2 * MF];        // w_cin3 folded with out_w tail
__device__ float         g_F[MF * MF * 64];    // fc1 lookup table [j][m][c]

// ---------------------------------------------------------------------------
// Prep kernels (cheap, run each launch; deterministic)
// ---------------------------------------------------------------------------
__global__ void prep_wsym(const float* __restrict__ w1) {
    int t = blockIdx.x;                 // 0..1175
    int k = 0, base = 0;
    while (t >= base + (MF - k)) { base += MF - k; ++k; }
    int j = k + (t - base);             // k <= j
    int o = threadIdx.x;                // 0..67
    float v = w1[(k * MF + j) * O1 + o];
    if (k < j) v += w1[(j * MF + k) * O1 + o];
    g_wsym[t * O1 + o] = v;
    if (o == 0) { g_pk[t] = (unsigned char)k; g_pj[t] = (unsigned char)j; }
}

__global__ void prep_V3(const float* __restrict__ w3, const float* __restrict__ out_w) {
    int n = blockIdx.x * blockDim.x + threadIdx.x;   // 0..1535
    if (n >= O2 * MF) return;
    float s = 0.f;
    #pragma unroll
    for (int o = 0; o < O3; ++o) s += w3[n * O3 + o] * out_w[25 + O1 + O2 + o];
    g_V3[n] = s;
}

__global__ void prep_F(const float* __restrict__ emb, const float* __restrict__ fc1_w) {
    __shared__ float er[DD];
    int jm = blockIdx.x;                 // j*48+m
    int m = jm % MF, j = jm / MF;
    int c = threadIdx.x;                 // 0..63
    for (int d = c; d < DD; d += 64) er[d] = emb[m * DD + d];
    __syncthreads();
    float s = 0.f;
    #pragma unroll 8
    for (int d = 0; d < DD; ++d) s += er[d] * fc1_w[(j * DD + d) * 64 + c];
    g_F[jm * 64 + c] = s;
}

// ---------------------------------------------------------------------------
// CTA-level GEMM:  C[O,128] = A[K,O]^T * P[K,128],
// where P[k,d] = U[idx_k(k), d] * V[idx_j(k), d] generated on the fly.
// ---------------------------------------------------------------------------
template<int O, int SLOTS, bool TRI>
__device__ __forceinline__ void cta_gemm(
    const float* __restrict__ Ag, int K,
    const float* __restrict__ U, const float* __restrict__ V,
    float* __restrict__ Csm, float* __restrict__ Asm, float* __restrict__ Psm,
    int tid)
{
    const int tx = tid & 31;   // column group: cols tx*4 .. tx*4+3
    const int ty = tid >> 5;   // row group: rows ty + 8*s
    float acc[SLOTS][4];
    #pragma unroll
    for (int s = 0; s < SLOTS; ++s)
        { acc[s][0] = 0.f; acc[s][1] = 0.f; acc[s][2] = 0.f; acc[s][3] = 0.f; }

    for (int k0 = 0; k0 < K; k0 += KT) {
        const int kt = min(KT, K - k0);
        __syncthreads();
        // stage A tile (coalesced from global/L2)
        for (int i = tid; i < kt * O; i += 256) Asm[i] = Ag[k0 * O + i];
        // stage P tile
        for (int i = tid; i < (kt << 7); i += 256) {
            int kk = i >> 7, d = i & 127;
            int kg = k0 + kk;
            int ks, js;
            if (TRI) { ks = (int)g_pk[kg]; js = (int)g_pj[kg]; }
            else     { ks = kg / MF;       js = kg - ks * MF; }
            Psm[i] = U[(ks << 7) + d] * V[(js << 7) + d];
        }
        __syncthreads();
        for (int kk = 0; kk < kt; ++kk) {
            const float4 pv = *(const float4*)(Psm + (kk << 7) + (tx << 2));
            const float* arow = Asm + kk * O;
            #pragma unroll
            for (int s = 0; s < SLOTS; ++s) {
                const int o = ty + (s << 3);
                if ((O & 7) && s == SLOTS - 1 && o >= O) continue;  // warp-uniform
                const float a = arow[o];
                acc[s][0] = fmaf(a, pv.x, acc[s][0]);
                acc[s][1] = fmaf(a, pv.y, acc[s][1]);
                acc[s][2] = fmaf(a, pv.z, acc[s][2]);
                acc[s][3] = fmaf(a, pv.w, acc[s][3]);
            }
        }
    }
    __syncthreads();
    #pragma unroll
    for (int s = 0; s < SLOTS; ++s) {
        const int o = ty + (s << 3);
        if (o < O) {
            float4 v; v.x = acc[s][0]; v.y = acc[s][1]; v.z = acc[s][2]; v.w = acc[s][3];
            *(float4*)(Csm + (o << 7) + (tx << 2)) = v;
        }
    }
    __syncthreads();
}

// ---------------------------------------------------------------------------
// Main fused kernel: one CTA per batch row.
// ---------------------------------------------------------------------------
// dyn smem layout (floats): x0 6144 | xk1 8704 | xk2 4096 | Asm 2176 | Psm 4096
#define SM_X0   0
#define SM_XK1  6144
#define SM_XK2  14848
#define SM_A    18944
#define SM_P    21120
#define SM_FLT  25216
#define SMEM_BYTES (SM_FLT * 4)

__global__ __launch_bounds__(256, 2) void cin_main(
    const int*   __restrict__ x,     const float* __restrict__ emb,
    const float* __restrict__ w2,
    const float* __restrict__ lin_w, const float* __restrict__ lin_b,
    const float* __restrict__ fc1_b,
    const float* __restrict__ bn1_g, const float* __restrict__ bn1_b,
    const float* __restrict__ fc2_w, const float* __restrict__ fc2_b,
    const float* __restrict__ bn2_g, const float* __restrict__ bn2_b,
    const float* __restrict__ fc3_w, const float* __restrict__ fc3_b,
    const float* __restrict__ bn3_g, const float* __restrict__ bn3_b,
    const float* __restrict__ out_w, const float* __restrict__ out_b,
    float* __restrict__ out)
{
    extern __shared__ float sm[];
    float* x0  = sm + SM_X0;
    float* xk1 = sm + SM_XK1;
    float* xk2 = sm + SM_XK2;
    float* Asm = sm + SM_A;
    float* Psm = sm + SM_P;
    __shared__ int   xr[MF];
    __shared__ float ows[152];
    __shared__ float d1s[64], d2s[48], d3s[24];
    __shared__ float red[8];

    const int tid = threadIdx.x;
    const int b   = blockIdx.x;

    if (tid < MF)  xr[tid]  = x[b * MF + tid];
    if (tid < 149) ows[tid] = out_w[tid];
    __syncthreads();

    // gather x0 = emb[x[b]]
    for (int i = tid; i < MF * DD; i += 256) {
        int j = i >> 7, d = i & 127;
        x0[i] = emb[(xr[j] << 7) + d];
    }
    // (cta_gemm begins with __syncthreads)

    // CIN layer 1 (symmetric-folded) and layer 2
    cta_gemm<O1, 9, true >(g_wsym, K1TRI, x0,  x0, xk1, Asm, Psm, tid);
    cta_gemm<O2, 4, false>(w2,     K2,    xk1, x0, xk2, Asm, Psm, tid);

    // stage V3 (reuse Asm region, 1536 <= 2176)
    for (int i = tid; i < O2 * MF; i += 256) Asm[i] = g_V3[i];
    __syncthreads();

    float part = 0.f;
    // layer-3 contribution (folded): sum_{k,d} xk2[k,d] * (V3 @ x0)[k,d]
    {
        const int tx = tid & 31, ty = tid >> 5;
        #pragma unroll
        for (int s = 0; s < 4; ++s) {
            const int r = ty + (s << 3);     // < 32
            const float* vrow = Asm + r * MF;
            float y0 = 0.f, y1 = 0.f, y2 = 0.f, y3 = 0.f;
            #pragma unroll 8
            for (int j = 0; j < MF; ++j) {
                const float v = vrow[j];
                const float4 xv = *(const float4*)(x0 + (j << 7) + (tx << 2));
                y0 = fmaf(v, xv.x, y0); y1 = fmaf(v, xv.y, y1);
                y2 = fmaf(v, xv.z, y2); y3 = fmaf(v, xv.w, y3);
            }
            const float4 kv = *(const float4*)(xk2 + (r << 7) + (tx << 2));
            part += y0 * kv.x + y1 * kv.y + y2 * kv.z + y3 * kv.w;
        }
    }
    // cin1 / cin2 sum-pools dotted with out_w
    for (int i = tid; i < O1 * DD; i += 256) part += xk1[i] * ows[25 + (i >> 7)];
    for (int i = tid; i < O2 * DD; i += 256) part += xk2[i] * ows[25 + O1 + (i >> 7)];

    // block reduce
    #pragma unroll
    for (int off = 16; off; off >>= 1) part += __shfl_xor_sync(0xffffffffu, part, off);
    if ((tid & 31) == 0) red[tid >> 5] = part;
    __syncthreads();

    // deep MLP
    const float invs = rsqrtf(1.0f + 1e-3f);
    if (tid < 64) {
        float a = fc1_b[tid];
        #pragma unroll
        for (int j = 0; j < MF; ++j) a += g_F[((j * MF + xr[j]) << 6) + tid];
        a = fmaxf(a, 0.f);
        d1s[tid] = bn1_g[tid] * a * invs + bn1_b[tid];
    }
    __syncthreads();
    if (tid < 48) {
        float a = fc2_b[tid];
        #pragma unroll 8
        for (int i = 0; i < 64; ++i) a += d1s[i] * fc2_w[i * 48 + tid];
        a = tanhf(a);
        d2s[tid] = bn2_g[tid] * a * invs + bn2_b[tid];
    }
    __syncthreads();
    if (tid < 24) {
        float a = fc3_b[tid];
        #pragma unroll 8
        for (int i = 0; i < 48; ++i) a += d2s[i] * fc3_w[i * 24 + tid];
        a = tanhf(a);
        d3s[tid] = bn3_g[tid] * a * invs + bn3_b[tid];
    }
    __syncthreads();
    if (tid == 0) {
        float lg = out_b[0];
        #pragma unroll
        for (int w = 0; w < 8; ++w) lg += red[w];
        #pragma unroll
        for (int c = 0; c < 24; ++c) lg += d3s[c] * ows[c];
        float sl = lin_b[0];
        #pragma unroll
        for (int j = 0; j < MF; ++j) sl += (float)xr[j] * lin_w[j];
        lg += tanhf(sl) * ows[24];
        out[b] = 1.0f / (1.0f + expf(-lg));
    }
}

// ---------------------------------------------------------------------------
// Launch
// ---------------------------------------------------------------------------
extern "C" void kernel_launch(void* const* d_in, const int* in_sizes, int n_in,
                              void* d_out, int out_size)
{
    const int*   x     = (const int*)  d_in[0];
    const float* emb   = (const float*)d_in[1];
    const float* w1    = (const float*)d_in[2];
    const float* w2    = (const float*)d_in[3];
    const float* w3    = (const float*)d_in[4];
    const float* lin_w = (const float*)d_in[5];
    const float* lin_b = (const float*)d_in[6];
    const float* fc1_w = (const float*)d_in[7];
    const float* fc1_b = (const float*)d_in[8];
    const float* bn1_g = (const float*)d_in[9];
    const float* bn1_b = (const float*)d_in[10];
    const float* fc2_w = (const float*)d_in[11];
    const float* fc2_b = (const float*)d_in[12];
    const float* bn2_g = (const float*)d_in[13];
    const float* bn2_b = (const float*)d_in[14];
    const float* fc3_w = (const float*)d_in[15];
    const float* fc3_b = (const float*)d_in[16];
    const float* bn3_g = (const float*)d_in[17];
    const float* bn3_b = (const float*)d_in[18];
    const float* out_w = (const float*)d_in[19];
    const float* out_b = (const float*)d_in[20];
    float* out = (float*)d_out;

    prep_wsym<<<K1TRI, O1>>>(w1);
    prep_V3<<<6, 256>>>(w3, out_w);
    prep_F<<<MF * MF, 64>>>(emb, fc1_w);

    cudaFuncSetAttribute(cin_main, cudaFuncAttributeMaxDynamicSharedMemorySize, SMEM_BYTES);
    cin_main<<<BATCH, 256, SMEM_BYTES>>>(
        x, emb, w2, lin_w, lin_b, fc1_b, bn1_g, bn1_b,
        fc2_w, fc2_b, bn2_g, bn2_b, fc3_w, fc3_b, bn3_g, bn3_b,
        out_w, out_b, out);
}

// round 5
// speedup vs baseline: 7.9638x; 7.9638x over previous
#include <cuda_runtime.h>
#include <cuda_bf16.h>
#include <math.h>
#include <stdint.h>

// ---------------------------------------------------------------------------
// Problem constants
// ---------------------------------------------------------------------------
#define BATCH 512
#define MF    48
#define DD    128
#define O1    68
#define O2    32
#define O3    24
#define NPAIR 1176          // 48*49/2 symmetric pairs
#define KDIAG 1224          // + 48 linear (diag) rows
#define KPAD  1280          // padded to 20 tiles of 64
#define NG    144           // GEMM N: 68 xk1 + 4 pad + 68 R' + 4 pad
#define NKT   20            // k-tiles of 64
#define KT    64
#define TILEB (NG*KT*2)     // 18432 bytes per B tile
#define XST   50            // x0t row stride (48 data + 1.0 + 0.0)

// ---------------------------------------------------------------------------
// Device-global scratch (no allocation allowed)
// ---------------------------------------------------------------------------
__device__ float g_wsym[NPAIR * O1];
__device__ float g_V3[O2 * MF];
__device__ float g_Tq[O1 * NPAIR];
__device__ float g_c[O1 * MF];
__device__ unsigned int g_suv[KPAD];
__device__ __align__(16) __nv_bfloat16 g_Bt[NKT * NG * KT];  // packed+swizzled
__device__ float g_F[MF * MF * 64];                          // fc1 lookup

// ---------------------------------------------------------------------------
// Helpers
// ---------------------------------------------------------------------------
__device__ __forceinline__ void pair_decode(int t, int& u, int& v) {
    int k = 0, base = 0;
    while (t >= base + (MF - k)) { base += MF - k; ++k; }
    u = k; v = k + (t - base);
}

__device__ __forceinline__ uint32_t smem_u32(const void* p) {
    uint32_t a;
    asm("{ .reg .u64 t; cvta.to.shared.u64 t, %1; cvt.u32.u64 %0, t; }" : "=r"(a) : "l"(p));
    return a;
}

__device__ __forceinline__ uint32_t pack_bf16(float a, float b) {
    __nv_bfloat162 h = __floats2bfloat162_rn(a, b);   // a -> low, b -> high
    return *reinterpret_cast<uint32_t*>(&h);
}

__device__ __forceinline__ void ldsm_x4(uint32_t& r0, uint32_t& r1,
                                        uint32_t& r2, uint32_t& r3, uint32_t addr) {
    asm volatile("ldmatrix.sync.aligned.m8n8.x4.shared.b16 {%0,%1,%2,%3}, [%4];"
                 : "=r"(r0), "=r"(r1), "=r"(r2), "=r"(r3) : "r"(addr));
}

__device__ __forceinline__ void mma16816(float* c, uint32_t a0, uint32_t a1,
                                         uint32_t a2, uint32_t a3,
                                         uint32_t b0, uint32_t b1) {
    asm volatile(
        "mma.sync.aligned.m16n8k16.row.col.f32.bf16.bf16.f32 "
        "{%0,%1,%2,%3}, {%4,%5,%6,%7}, {%8,%9}, {%0,%1,%2,%3};"
        : "+f"(c[0]), "+f"(c[1]), "+f"(c[2]), "+f"(c[3])
        : "r"(a0), "r"(a1), "r"(a2), "r"(a3), "r"(b0), "r"(b1));
}

// ---------------------------------------------------------------------------
// Prep kernels (sample-independent; run every launch; deterministic)
// ---------------------------------------------------------------------------
__global__ void prep_wsym(const float* __restrict__ w1) {
    int t = blockIdx.x; int u, v; pair_decode(t, u, v);
    int o = threadIdx.x;
    float val = w1[(u * MF + v) * O1 + o];
    if (u < v) val += w1[(v * MF + u) * O1 + o];
    g_wsym[t * O1 + o] = val;
}

__global__ void prep_suv() {
    int k = blockIdx.x * 256 + threadIdx.x;
    if (k >= KPAD) return;
    int u, v;
    if (k < NPAIR)      { pair_decode(k, u, v); }
    else if (k < KDIAG) { u = k - NPAIR; v = 48; }   // x0[u] * 1.0
    else                { u = 49; v = 49; }          // 0.0 * 0.0
    g_suv[k] = (unsigned)u | ((unsigned)v << 16);
}

__global__ void prep_V3(const float* __restrict__ w3, const float* __restrict__ out_w) {
    int n = blockIdx.x * blockDim.x + threadIdx.x;
    if (n >= O2 * MF) return;
    float s = 0.f;
    #pragma unroll
    for (int o = 0; o < O3; ++o) s += w3[n * O3 + o] * out_w[25 + O1 + O2 + o];
    g_V3[n] = s;
}

__global__ void prep_c(const float* __restrict__ w2, const float* __restrict__ out_w) {
    int n = blockIdx.x * 256 + threadIdx.x;
    if (n >= O1 * MF) return;
    float s = 0.f;
    #pragma unroll
    for (int k2 = 0; k2 < O2; ++k2) s += w2[n * O2 + k2] * out_w[25 + O1 + k2];
    g_c[n] = s;
}

__global__ void prep_Tq(const float* __restrict__ w2) {
    __shared__ float sV[O2 * MF];
    int t = blockIdx.x;                // pair index
    int a = threadIdx.x;               // 0..67
    for (int i = a; i < O2 * MF; i += O1) sV[i] = g_V3[i];
    __syncthreads();
    int u, v; pair_decode(t, u, v);
    float s = 0.f;
    const float* r1 = w2 + (a * MF + u) * O2;
    #pragma unroll 8
    for (int k2 = 0; k2 < O2; ++k2) s += r1[k2] * sV[k2 * MF + v];
    if (u < v) {
        const float* r2 = w2 + (a * MF + v) * O2;
        #pragma unroll 8
        for (int k2 = 0; k2 < O2; ++k2) s += r2[k2] * sV[k2 * MF + u];
    }
    g_Tq[a * NPAIR + t] = s;
}

// pack B tiles: storage [tile][n:144][k:64] bf16, 16B chunks XOR-swizzled by n&7
__global__ void prep_pack() {
    int idx = blockIdx.x * 256 + threadIdx.x;
    if (idx >= NKT * NG * KT) return;
    int t = idx / (NG * KT);
    int r = idx - t * (NG * KT);
    int n = r >> 6, kk = r & 63;
    int k = t * 64 + kk;
    float val = 0.f;
    if (n < O1) {
        if (k < NPAIR) val = g_wsym[k * O1 + n];
    } else if (n >= 72 && n < 72 + O1) {
        int a = n - 72;
        if (k < NPAIR)      val = g_Tq[a * NPAIR + k];
        else if (k < KDIAG) val = g_c[a * MF + (k - NPAIR)];
    }
    int chunk = kk >> 3;
    int off = t * TILEB + n * 128 + ((chunk ^ (n & 7)) << 4) + ((kk & 7) << 1);
    *(__nv_bfloat16*)((char*)g_Bt + off) = __float2bfloat16_rn(val);
}

__global__ void prep_F(const float* __restrict__ emb, const float* __restrict__ fc1_w) {
    __shared__ float er[DD];
    int jm = blockIdx.x;
    int m = jm % MF, j = jm / MF;
    int c = threadIdx.x;               // 0..63
    for (int d = c; d < DD; d += 64) er[d] = emb[m * DD + d];
    __syncthreads();
    float s = 0.f;
    #pragma unroll 8
    for (int d = 0; d < DD; ++d) s += er[d] * fc1_w[(j * DD + d) * 64 + c];
    g_F[jm * 64 + c] = s;
}

// ---------------------------------------------------------------------------
// Main fused kernel: one CTA per batch row. HMMA GEMM C[128(d),144] in regs.
// ---------------------------------------------------------------------------
// dyn smem layout (bytes, from 1024-aligned base)
#define OFF_X0T   0                    // 128*50 f32 = 25600
#define OFF_B     25600                // 2 * 18432 = 36864
#define OFF_SUV   62464                // 1280 u32  = 5120
#define OFF_OWP   67584                // 144 f32   = 576
#define OFF_XR    68160                // 48 int
#define OFF_D1    68352                // 64 f32
#define OFF_D2    68608                // 48 f32
#define OFF_D3    68800                // 24 f32
#define OFF_RED   68896                // 8 f32
#define SMEM_DYN  (68928 + 1024)

__global__ __launch_bounds__(256, 2) void cin_main(
    const int*   __restrict__ x,     const float* __restrict__ emb,
    const float* __restrict__ lin_w, const float* __restrict__ lin_b,
    const float* __restrict__ fc1_b,
    const float* __restrict__ bn1_g, const float* __restrict__ bn1_b,
    const float* __restrict__ fc2_w, const float* __restrict__ fc2_b,
    const float* __restrict__ bn2_g, const float* __restrict__ bn2_b,
    const float* __restrict__ fc3_w, const float* __restrict__ fc3_b,
    const float* __restrict__ bn3_g, const float* __restrict__ bn3_b,
    const float* __restrict__ out_w, const float* __restrict__ out_b,
    float* __restrict__ out)
{
    extern __shared__ char smraw[];
    char* sm = (char*)(((uintptr_t)smraw + 1023) & ~(uintptr_t)1023);
    float*        x0t  = (float*)(sm + OFF_X0T);
    unsigned int* ssuv = (unsigned int*)(sm + OFF_SUV);
    float*        owp  = (float*)(sm + OFF_OWP);
    int*          xr   = (int*)(sm + OFF_XR);
    float*        d1s  = (float*)(sm + OFF_D1);
    float*        d2s  = (float*)(sm + OFF_D2);
    float*        d3s  = (float*)(sm + OFF_D3);
    float*        red  = (float*)(sm + OFF_RED);

    const int tid  = threadIdx.x;
    const int b    = blockIdx.x;
    const int lane = tid & 31;
    const int warp = tid >> 5;
    const uint32_t s32 = smem_u32(sm);

    if (tid < MF) xr[tid] = x[b * MF + tid];
    for (int i = tid; i < NG; i += 256) owp[i] = (i < O1) ? out_w[25 + i] : 0.f;
    for (int i = tid; i < KPAD; i += 256) ssuv[i] = g_suv[i];
    __syncthreads();

    // gather x0 transposed with sentinel cols: x0t[d*50 + j], col48=1, col49=0
    for (int i = tid; i < DD * XST; i += 256) {
        int d = i / XST, j = i - d * XST;
        float v;
        if (j < MF)       v = emb[(xr[j] << 7) + d];
        else if (j == 48) v = 1.0f;
        else              v = 0.0f;
        x0t[i] = v;
    }

    // prologue: stage B tile 0
    {
        const uint4* src = (const uint4*)((const char*)g_Bt);
        uint4* dst = (uint4*)(sm + OFF_B);
        for (int i = tid; i < TILEB / 16; i += 256) dst[i] = src[i];
    }
    __syncthreads();

    // per-thread fragment geometry
    const int mrow0 = (warp * 16 + (lane >> 2)) * XST;  // x0t offset of row g
    const int mrow1 = mrow0 + 8 * XST;                  // row g+8
    const int kq    = (lane & 3) << 1;                  // k offset within step
    const int matq  = lane >> 3;                        // ldmatrix matrix id
    const int nloc  = ((matq >= 2) ? 8 : 0) + (lane & 7);
    const int cksel = matq & 1;

    float acc[18][4];
    #pragma unroll
    for (int i = 0; i < 18; ++i)
        { acc[i][0] = 0.f; acc[i][1] = 0.f; acc[i][2] = 0.f; acc[i][3] = 0.f; }

    for (int t = 0; t < NKT; ++t) {
        // stage next tile into the other buffer (LDG overlaps HMMA below)
        if (t < NKT - 1) {
            const uint4* src = (const uint4*)((const char*)g_Bt + (t + 1) * TILEB);
            uint4* dst = (uint4*)(sm + OFF_B + ((t + 1) & 1) * TILEB);
            for (int i = tid; i < TILEB / 16; i += 256) dst[i] = src[i];
        }
        const uint32_t Bb = s32 + OFF_B + (t & 1) * TILEB;
        const int k0 = t * 64;

        #pragma unroll
        for (int s = 0; s < 4; ++s) {
            const int ks = s << 4;
            const int kg = k0 + ks + kq;
            // ---- A fragment from x0t (no smem staging) ----
            unsigned p0 = ssuv[kg],     p1 = ssuv[kg + 1];
            unsigned p8 = ssuv[kg + 8], p9 = ssuv[kg + 9];
            float v00 = x0t[mrow0 + (p0 & 0xFFFF)] * x0t[mrow0 + (p0 >> 16)];
            float v01 = x0t[mrow0 + (p1 & 0xFFFF)] * x0t[mrow0 + (p1 >> 16)];
            float v10 = x0t[mrow1 + (p0 & 0xFFFF)] * x0t[mrow1 + (p0 >> 16)];
            float v11 = x0t[mrow1 + (p1 & 0xFFFF)] * x0t[mrow1 + (p1 >> 16)];
            float v02 = x0t[mrow0 + (p8 & 0xFFFF)] * x0t[mrow0 + (p8 >> 16)];
            float v03 = x0t[mrow0 + (p9 & 0xFFFF)] * x0t[mrow0 + (p9 >> 16)];
            float v12 = x0t[mrow1 + (p8 & 0xFFFF)] * x0t[mrow1 + (p8 >> 16)];
            float v13 = x0t[mrow1 + (p9 & 0xFFFF)] * x0t[mrow1 + (p9 >> 16)];
            uint32_t a0 = pack_bf16(v00, v01);
            uint32_t a1 = pack_bf16(v10, v11);
            uint32_t a2 = pack_bf16(v02, v03);
            uint32_t a3 = pack_bf16(v12, v13);

            const int chunk = (ks >> 3) + cksel;
            #pragma unroll
            for (int q = 0; q < 9; ++q) {
                const int n = q * 16 + nloc;
                uint32_t baddr = Bb + n * 128 + (uint32_t)((chunk ^ (n & 7)) << 4);
                uint32_t b0, b1, b2, b3;
                ldsm_x4(b0, b1, b2, b3, baddr);
                mma16816(acc[2 * q],     a0, a1, a2, a3, b0, b1);
                mma16816(acc[2 * q + 1], a0, a1, a2, a3, b2, b3);
            }
        }
        __syncthreads();
    }

    // ---- epilogue straight from accumulator registers ----
    // C element (thread,r,nt): row = warp*16 + lane/4 + 8*(r>>1),
    //                          col = nt*8 + (lane&3)*2 + (r&1)
    float part = 0.f;
    #pragma unroll
    for (int nt = 0; nt < 9; ++nt) {
        const float w0 = owp[nt * 8 + kq];
        const float w1v = owp[nt * 8 + kq + 1];
        #pragma unroll
        for (int r = 0; r < 4; ++r) {
            float xv = acc[nt][r];
            part += xv * acc[nt + 9][r] + ((r & 1) ? w1v : w0) * xv;
        }
    }
    #pragma unroll
    for (int off = 16; off; off >>= 1)
        part += __shfl_xor_sync(0xffffffffu, part, off);
    if (lane == 0) red[warp] = part;

    // ---- deep MLP (fp32 exact) ----
    const float invs = rsqrtf(1.0f + 1e-3f);
    __syncthreads();
    if (tid < 64) {
        float a = fc1_b[tid];
        #pragma unroll
        for (int j = 0; j < MF; ++j) a += g_F[((j * MF + xr[j]) << 6) + tid];
        a = fmaxf(a, 0.f);
        d1s[tid] = bn1_g[tid] * a * invs + bn1_b[tid];
    }
    __syncthreads();
    if (tid < 48) {
        float a = fc2_b[tid];
        #pragma unroll 8
        for (int i = 0; i < 64; ++i) a += d1s[i] * fc2_w[i * 48 + tid];
        a = tanhf(a);
        d2s[tid] = bn2_g[tid] * a * invs + bn2_b[tid];
    }
    __syncthreads();
    if (tid < 24) {
        float a = fc3_b[tid];
        #pragma unroll 8
        for (int i = 0; i < 48; ++i) a += d2s[i] * fc3_w[i * 24 + tid];
        a = tanhf(a);
        d3s[tid] = bn3_g[tid] * a * invs + bn3_b[tid];
    }
    __syncthreads();

    if (tid == 0) {
        float lg = out_b[0];
        #pragma unroll
        for (int w = 0; w < 8; ++w) lg += red[w];
        #pragma unroll
        for (int c = 0; c < 24; ++c) lg += d3s[c] * out_w[c];
        float sl = lin_b[0];
        #pragma unroll
        for (int j = 0; j < MF; ++j) sl += (float)xr[j] * lin_w[j];
        lg += tanhf(sl) * out_w[24];
        out[b] = 1.0f / (1.0f + expf(-lg));
    }
}

// ---------------------------------------------------------------------------
// Launch
// ---------------------------------------------------------------------------
extern "C" void kernel_launch(void* const* d_in, const int* in_sizes, int n_in,
                              void* d_out, int out_size)
{
    const int*   x     = (const int*)  d_in[0];
    const float* emb   = (const float*)d_in[1];
    const float* w1    = (const float*)d_in[2];
    const float* w2    = (const float*)d_in[3];
    const float* w3    = (const float*)d_in[4];
    const float* lin_w = (const float*)d_in[5];
    const float* lin_b = (const float*)d_in[6];
    const float* fc1_w = (const float*)d_in[7];
    const float* fc1_b = (const float*)d_in[8];
    const float* bn1_g = (const float*)d_in[9];
    const float* bn1_b = (const float*)d_in[10];
    const float* fc2_w = (const float*)d_in[11];
    const float* fc2_b = (const float*)d_in[12];
    const float* bn2_g = (const float*)d_in[13];
    const float* bn2_b = (const float*)d_in[14];
    const float* fc3_w = (const float*)d_in[15];
    const float* fc3_b = (const float*)d_in[16];
    const float* bn3_g = (const float*)d_in[17];
    const float* bn3_b = (const float*)d_in[18];
    const float* out_w = (const float*)d_in[19];
    const float* out_b = (const float*)d_in[20];
    float* out = (float*)d_out;

    prep_wsym<<<NPAIR, O1>>>(w1);
    prep_suv<<<(KPAD + 255) / 256, 256>>>();
    prep_V3<<<(O2 * MF + 255) / 256, 256>>>(w3, out_w);
    prep_c<<<(O1 * MF + 255) / 256, 256>>>(w2, out_w);
    prep_Tq<<<NPAIR, O1>>>(w2);
    prep_pack<<<(NKT * NG * KT + 255) / 256, 256>>>();
    prep_F<<<MF * MF, 64>>>(emb, fc1_w);

    cudaFuncSetAttribute(cin_main, cudaFuncAttributeMaxDynamicSharedMemorySize, SMEM_DYN);
    cin_main<<<BATCH, 256, SMEM_DYN>>>(
        x, emb, lin_w, lin_b, fc1_b, bn1_g, bn1_b,
        fc2_w, fc2_b, bn2_g, bn2_b, fc3_w, fc3_b, bn3_g, bn3_b,
        out_w, out_b, out);
}

// round 6
// speedup vs baseline: 9.0351x; 1.1345x over previous
#include <cuda_runtime.h>
#include <cuda_bf16.h>
#include <math.h>
#include <stdint.h>

// ---------------------------------------------------------------------------
// Problem constants
// ---------------------------------------------------------------------------
#define BATCH 512
#define MF    48
#define DD    128
#define O1    68
#define O2    32
#define O3    24
#define NPAIR 1176          // 48*49/2 symmetric pairs
#define KDIAG 1224          // + 48 linear (diag) rows
#define KPAD  1280          // padded to 20 tiles of 64
#define NG    144           // GEMM N: 68 xk1 + 4 pad + 68 R' + 4 pad
#define NKT   20            // k-tiles of 64
#define KT    64
#define TILEB (NG*KT*2)     // 18432 bytes per B tile
#define XST   50            // x0t row stride (48 data + 1.0 + 0.0)

// ---------------------------------------------------------------------------
// Device-global scratch (no allocation allowed)
// ---------------------------------------------------------------------------
__device__ float g_V3[O2 * MF];
__device__ unsigned int g_suv[KPAD];
__device__ __align__(16) __nv_bfloat16 g_Bt[NKT * NG * KT];  // packed+swizzled
__device__ float g_F[MF * MF * 64];                          // fc1 lookup

// ---------------------------------------------------------------------------
// Helpers
// ---------------------------------------------------------------------------
__device__ __forceinline__ void pair_decode(int t, int& u, int& v) {
    int k = 0, base = 0;
    while (t >= base + (MF - k)) { base += MF - k; ++k; }
    u = k; v = k + (t - base);
}

__device__ __forceinline__ uint32_t smem_u32(const void* p) {
    uint32_t a;
    asm("{ .reg .u64 t; cvta.to.shared.u64 t, %1; cvt.u32.u64 %0, t; }" : "=r"(a) : "l"(p));
    return a;
}

__device__ __forceinline__ uint32_t pack_bf16(float a, float b) {
    __nv_bfloat162 h = __floats2bfloat162_rn(a, b);   // a -> low, b -> high
    return *reinterpret_cast<uint32_t*>(&h);
}

__device__ __forceinline__ void ldsm_x4(uint32_t& r0, uint32_t& r1,
                                        uint32_t& r2, uint32_t& r3, uint32_t addr) {
    asm volatile("ldmatrix.sync.aligned.m8n8.x4.shared.b16 {%0,%1,%2,%3}, [%4];"
                 : "=r"(r0), "=r"(r1), "=r"(r2), "=r"(r3) : "r"(addr));
}

__device__ __forceinline__ void mma16816(float* c, uint32_t a0, uint32_t a1,
                                         uint32_t a2, uint32_t a3,
                                         uint32_t b0, uint32_t b1) {
    asm volatile(
        "mma.sync.aligned.m16n8k16.row.col.f32.bf16.bf16.f32 "
        "{%0,%1,%2,%3}, {%4,%5,%6,%7}, {%8,%9}, {%0,%1,%2,%3};"
        : "+f"(c[0]), "+f"(c[1]), "+f"(c[2]), "+f"(c[3])
        : "r"(a0), "r"(a1), "r"(a2), "r"(a3), "r"(b0), "r"(b1));
}

// ---------------------------------------------------------------------------
// prep1: suv table + V3 + fc1 lookup table (smem-tiled per-j GEMM)
//   blocks [0,11): suv + V3 elementwise
//   blocks [11,59): j = blk-11, F_j[48,64] = emb[48,128] @ fc1_w_j[128,64]
// dynamic smem: 6144*4 + 8192*4 = 57344 bytes (F blocks only)
// ---------------------------------------------------------------------------
#define PREP1_SMEM (6144*4 + 8192*4)
__global__ void prep1(const float* __restrict__ w3, const float* __restrict__ out_w,
                      const float* __restrict__ emb, const float* __restrict__ fc1_w) {
    extern __shared__ float p1s[];
    const int tid = threadIdx.x;
    if (blockIdx.x < 11) {
        int gid = blockIdx.x * 256 + tid;
        if (gid < KPAD) {
            int u, v;
            if (gid < NPAIR)      { pair_decode(gid, u, v); }
            else if (gid < KDIAG) { u = gid - NPAIR; v = 48; }
            else                  { u = 49; v = 49; }
            g_suv[gid] = (unsigned)u | ((unsigned)v << 16);
        } else if (gid < KPAD + O2 * MF) {
            int n = gid - KPAD;
            float s = 0.f;
            #pragma unroll
            for (int o = 0; o < O3; ++o) s += w3[n * O3 + o] * out_w[25 + O1 + O2 + o];
            g_V3[n] = s;
        }
        return;
    }
    // F blocks
    float* se = p1s;           // emb, 6144 floats (entire table)
    float* sw = p1s + 6144;    // fc1_w slice j: 8192 floats
    const int j = blockIdx.x - 11;
    for (int i = tid; i < 6144; i += 256) se[i] = emb[i];
    for (int i = tid; i < 8192; i += 256) sw[i] = fc1_w[j * 8192 + i];
    __syncthreads();
    #pragma unroll
    for (int t = 0; t < 12; ++t) {
        int o = tid + t * 256;             // < 3072
        int m = o >> 6, c = o & 63;
        float s = 0.f;
        #pragma unroll 8
        for (int d = 0; d < DD; ++d) s += se[m * DD + d] * sw[d * 64 + c];
        g_F[(j * MF + m) * 64 + c] = s;
    }
}

// ---------------------------------------------------------------------------
// prep2: pack B tiles directly (inlines wsym / Tq / c algebra).
// storage [tile][n:144][k:64] bf16, 16B chunks XOR-swizzled by n&7
// ---------------------------------------------------------------------------
__global__ void prep2(const float* __restrict__ w1, const float* __restrict__ w2,
                      const float* __restrict__ out_w) {
    __shared__ float sV[O2 * MF];
    const int tid = threadIdx.x;
    for (int i = tid; i < O2 * MF; i += 256) sV[i] = g_V3[i];
    __syncthreads();

    int idx = blockIdx.x * 256 + tid;      // < NKT*NG*KT = 184320
    int t = idx / (NG * KT);
    int r = idx - t * (NG * KT);
    int n = r >> 6, kk = r & 63;
    int k = t * 64 + kk;
    float val = 0.f;
    if (n < O1) {
        if (k < NPAIR) {
            int u, v; pair_decode(k, u, v);
            val = w1[(u * MF + v) * O1 + n];
            if (u < v) val += w1[(v * MF + u) * O1 + n];
        }
    } else if (n >= 72 && n < 72 + O1) {
        int a = n - 72;
        if (k < NPAIR) {
            int u, v; pair_decode(k, u, v);
            float s = 0.f;
            const float* r1 = w2 + (a * MF + u) * O2;
            #pragma unroll 8
            for (int k2 = 0; k2 < O2; ++k2) s += r1[k2] * sV[k2 * MF + v];
            if (u < v) {
                const float* r2 = w2 + (a * MF + v) * O2;
                #pragma unroll 8
                for (int k2 = 0; k2 < O2; ++k2) s += r2[k2] * sV[k2 * MF + u];
            }
            val = s;
        } else if (k < KDIAG) {
            int m = k - NPAIR;
            float s = 0.f;
            const float* r1 = w2 + (a * MF + m) * O2;
            #pragma unroll 8
            for (int k2 = 0; k2 < O2; ++k2) s += r1[k2] * out_w[25 + O1 + k2];
            val = s;
        }
    }
    int chunk = kk >> 3;
    int off = t * TILEB + n * 128 + ((chunk ^ (n & 7)) << 4) + ((kk & 7) << 1);
    *(__nv_bfloat16*)((char*)g_Bt + off) = __float2bfloat16_rn(val);
}

// ---------------------------------------------------------------------------
// Main fused kernel: one CTA per TWO batch rows. Each ldmatrix B fragment
// feeds 4 HMMAs (2 samples x 2 n-subtiles) -> halved smem B traffic.
// ---------------------------------------------------------------------------
// dyn smem layout (bytes, from 1024-aligned base)
#define OFF_X0T   0                    // 2 * 128*50 f32 = 51200
#define OFF_B     51200                // 2 * 18432 = 36864
#define OFF_SUV   88064                // 1280 u32  = 5120
#define OFF_OWP   93184                // 144 f32   = 576
#define OFF_XR    93760                // 2*48 int  = 384
#define OFF_D1    94144                // 2*64 f32
#define OFF_D2    94656                // 2*48 f32
#define OFF_D3    95040                // 2*24 f32
#define OFF_RED   95232                // 2*8 f32
#define SMEM_DYN  (95296 + 1024)

__global__ __launch_bounds__(256, 1) void cin_main(
    const int*   __restrict__ x,     const float* __restrict__ emb,
    const float* __restrict__ lin_w, const float* __restrict__ lin_b,
    const float* __restrict__ fc1_b,
    const float* __restrict__ bn1_g, const float* __restrict__ bn1_b,
    const float* __restrict__ fc2_w, const float* __restrict__ fc2_b,
    const float* __restrict__ bn2_g, const float* __restrict__ bn2_b,
    const float* __restrict__ fc3_w, const float* __restrict__ fc3_b,
    const float* __restrict__ bn3_g, const float* __restrict__ bn3_b,
    const float* __restrict__ out_w, const float* __restrict__ out_b,
    float* __restrict__ out)
{
    extern __shared__ char smraw[];
    char* sm = (char*)(((uintptr_t)smraw + 1023) & ~(uintptr_t)1023);
    float*        x0t  = (float*)(sm + OFF_X0T);    // [2][128][50]
    unsigned int* ssuv = (unsigned int*)(sm + OFF_SUV);
    float*        owp  = (float*)(sm + OFF_OWP);
    int*          xr   = (int*)(sm + OFF_XR);       // [2][48]
    float*        d1s  = (float*)(sm + OFF_D1);     // [2][64]
    float*        d2s  = (float*)(sm + OFF_D2);     // [2][48]
    float*        d3s  = (float*)(sm + OFF_D3);     // [2][24]
    float*        red  = (float*)(sm + OFF_RED);    // [2][8]

    const int tid  = threadIdx.x;
    const int lane = tid & 31;
    const int warp = tid >> 5;
    const uint32_t s32 = smem_u32(sm);

    if (tid < 2 * MF) xr[tid] = x[blockIdx.x * (2 * MF) + tid];
    for (int i = tid; i < NG; i += 256) owp[i] = (i < O1) ? out_w[25 + i] : 0.f;
    for (int i = tid; i < KPAD; i += 256) ssuv[i] = g_suv[i];
    __syncthreads();

    // gather both samples' x0 transposed with sentinels: x0t[smp*6400 + d*50 + j]
    for (int i = tid; i < 2 * DD * XST; i += 256) {
        int smp = i / (DD * XST);
        int rr  = i - smp * (DD * XST);
        int d = rr / XST, j = rr - d * XST;
        float v;
        if (j < MF)       v = emb[(xr[smp * MF + j] << 7) + d];
        else if (j == 48) v = 1.0f;
        else              v = 0.0f;
        x0t[i] = v;
    }

    // prologue: stage B tile 0
    {
        const uint4* src = (const uint4*)((const char*)g_Bt);
        uint4* dst = (uint4*)(sm + OFF_B);
        for (int i = tid; i < TILEB / 16; i += 256) dst[i] = src[i];
    }
    __syncthreads();

    // per-thread fragment geometry
    const int rbase = (warp * 16 + (lane >> 2)) * XST;
    const float* rA0 = x0t + rbase;              // sample0, row g
    const float* rA1 = rA0 + 8 * XST;            // sample0, row g+8
    const float* rB0 = x0t + 6400 + rbase;       // sample1
    const float* rB1 = rB0 + 8 * XST;
    const int kq    = (lane & 3) << 1;
    const int matq  = lane >> 3;
    const int nloc  = ((matq >= 2) ? 8 : 0) + (lane & 7);
    const int cksel = matq & 1;

    float accA[18][4], accB[18][4];
    #pragma unroll
    for (int i = 0; i < 18; ++i)
        #pragma unroll
        for (int r = 0; r < 4; ++r) { accA[i][r] = 0.f; accB[i][r] = 0.f; }

    for (int t = 0; t < NKT; ++t) {
        if (t < NKT - 1) {
            const uint4* src = (const uint4*)((const char*)g_Bt + (t + 1) * TILEB);
            uint4* dst = (uint4*)(sm + OFF_B + ((t + 1) & 1) * TILEB);
            for (int i = tid; i < TILEB / 16; i += 256) dst[i] = src[i];
        }
        const uint32_t Bb = s32 + OFF_B + (t & 1) * TILEB;
        const int k0 = t * 64;

        #pragma unroll
        for (int s = 0; s < 4; ++s) {
            const int ks = s << 4;
            const int kg = k0 + ks + kq;
            unsigned p0 = ssuv[kg],     p1 = ssuv[kg + 1];
            unsigned p8 = ssuv[kg + 8], p9 = ssuv[kg + 9];
            const int u0 = p0 & 0xFFFF, w0i = p0 >> 16;
            const int u1 = p1 & 0xFFFF, w1i = p1 >> 16;
            const int u8 = p8 & 0xFFFF, w8i = p8 >> 16;
            const int u9 = p9 & 0xFFFF, w9i = p9 >> 16;
            // sample0 fragments
            uint32_t a0 = pack_bf16(rA0[u0] * rA0[w0i], rA0[u1] * rA0[w1i]);
            uint32_t a1 = pack_bf16(rA1[u0] * rA1[w0i], rA1[u1] * rA1[w1i]);
            uint32_t a2 = pack_bf16(rA0[u8] * rA0[w8i], rA0[u9] * rA0[w9i]);
            uint32_t a3 = pack_bf16(rA1[u8] * rA1[w8i], rA1[u9] * rA1[w9i]);
            // sample1 fragments
            uint32_t c0 = pack_bf16(rB0[u0] * rB0[w0i], rB0[u1] * rB0[w1i]);
            uint32_t c1 = pack_bf16(rB1[u0] * rB1[w0i], rB1[u1] * rB1[w1i]);
            uint32_t c2 = pack_bf16(rB0[u8] * rB0[w8i], rB0[u9] * rB0[w9i]);
            uint32_t c3 = pack_bf16(rB1[u8] * rB1[w8i], rB1[u9] * rB1[w9i]);

            const int chunk = (ks >> 3) + cksel;
            #pragma unroll
            for (int q = 0; q < 9; ++q) {
                const int n = q * 16 + nloc;
                uint32_t baddr = Bb + n * 128 + (uint32_t)((chunk ^ (n & 7)) << 4);
                uint32_t b0, b1, b2, b3;
                ldsm_x4(b0, b1, b2, b3, baddr);
                mma16816(accA[2 * q],     a0, a1, a2, a3, b0, b1);
                mma16816(accA[2 * q + 1], a0, a1, a2, a3, b2, b3);
                mma16816(accB[2 * q],     c0, c1, c2, c3, b0, b1);
                mma16816(accB[2 * q + 1], c0, c1, c2, c3, b2, b3);
            }
        }
        __syncthreads();
    }

    // ---- epilogue straight from accumulator registers ----
    float partA = 0.f, partB = 0.f;
    #pragma unroll
    for (int nt = 0; nt < 9; ++nt) {
        const float w0 = owp[nt * 8 + kq];
        const float w1v = owp[nt * 8 + kq + 1];
        #pragma unroll
        for (int r = 0; r < 4; ++r) {
            float wv = (r & 1) ? w1v : w0;
            float xa = accA[nt][r];
            partA += xa * accA[nt + 9][r] + wv * xa;
            float xb = accB[nt][r];
            partB += xb * accB[nt + 9][r] + wv * xb;
        }
    }
    #pragma unroll
    for (int off = 16; off; off >>= 1) {
        partA += __shfl_xor_sync(0xffffffffu, partA, off);
        partB += __shfl_xor_sync(0xffffffffu, partB, off);
    }
    if (lane == 0) { red[warp] = partA; red[8 + warp] = partB; }

    // ---- deep MLP (fp32 exact): half-block per sample ----
    const int smp = tid >> 7;      // 0 or 1
    const int t1  = tid & 127;
    const int* xrs = xr + smp * MF;
    const float invs = rsqrtf(1.0f + 1e-3f);
    __syncthreads();
    if (t1 < 64) {
        float a = fc1_b[t1];
        #pragma unroll
        for (int j = 0; j < MF; ++j) a += g_F[((j * MF + xrs[j]) << 6) + t1];
        a = fmaxf(a, 0.f);
        d1s[smp * 64 + t1] = bn1_g[t1] * a * invs + bn1_b[t1];
    }
    __syncthreads();
    if (t1 < 48) {
        float a = fc2_b[t1];
        const float* d1 = d1s + smp * 64;
        #pragma unroll 8
        for (int i = 0; i < 64; ++i) a += d1[i] * fc2_w[i * 48 + t1];
        a = tanhf(a);
        d2s[smp * 48 + t1] = bn2_g[t1] * a * invs + bn2_b[t1];
    }
    __syncthreads();
    if (t1 < 24) {
        float a = fc3_b[t1];
        const float* d2 = d2s + smp * 48;
        #pragma unroll 8
        for (int i = 0; i < 48; ++i) a += d2[i] * fc3_w[i * 24 + t1];
        a = tanhf(a);
        d3s[smp * 24 + t1] = bn3_g[t1] * a * invs + bn3_b[t1];
    }
    __syncthreads();

    if (t1 == 0) {
        float lg = out_b[0];
        #pragma unroll
        for (int w = 0; w < 8; ++w) lg += red[smp * 8 + w];
        const float* d3 = d3s + smp * 24;
        #pragma unroll
        for (int c = 0; c < 24; ++c) lg += d3[c] * out_w[c];
        float sl = lin_b[0];
        #pragma unroll
        for (int j = 0; j < MF; ++j) sl += (float)xrs[j] * lin_w[j];
        lg += tanhf(sl) * out_w[24];
        out[blockIdx.x * 2 + smp] = 1.0f / (1.0f + expf(-lg));
    }
}

// ---------------------------------------------------------------------------
// Launch
// ---------------------------------------------------------------------------
extern "C" void kernel_launch(void* const* d_in, const int* in_sizes, int n_in,
                              void* d_out, int out_size)
{
    const int*   x     = (const int*)  d_in[0];
    const float* emb   = (const float*)d_in[1];
    const float* w1    = (const float*)d_in[2];
    const float* w2    = (const float*)d_in[3];
    const float* w3    = (const float*)d_in[4];
    const float* lin_w = (const float*)d_in[5];
    const float* lin_b = (const float*)d_in[6];
    const float* fc1_w = (const float*)d_in[7];
    const float* fc1_b = (const float*)d_in[8];
    const float* bn1_g = (const float*)d_in[9];
    const float* bn1_b = (const float*)d_in[10];
    const float* fc2_w = (const float*)d_in[11];
    const float* fc2_b = (const float*)d_in[12];
    const float* bn2_g = (const float*)d_in[13];
    const float* bn2_b = (const float*)d_in[14];
    const float* fc3_w = (const float*)d_in[15];
    const float* fc3_b = (const float*)d_in[16];
    const float* bn3_g = (const float*)d_in[17];
    const float* bn3_b = (const float*)d_in[18];
    const float* out_w = (const float*)d_in[19];
    const float* out_b = (const float*)d_in[20];
    float* out = (float*)d_out;

    cudaFuncSetAttribute(prep1, cudaFuncAttributeMaxDynamicSharedMemorySize, PREP1_SMEM);
    prep1<<<59, 256, PREP1_SMEM>>>(w3, out_w, emb, fc1_w);
    prep2<<<NKT * NG * KT / 256, 256>>>(w1, w2, out_w);

    cudaFuncSetAttribute(cin_main, cudaFuncAttributeMaxDynamicSharedMemorySize, SMEM_DYN);
    cin_main<<<BATCH / 2, 256, SMEM_DYN>>>(
        x, emb, lin_w, lin_b, fc1_b, bn1_g, bn1_b,
        fc2_w, fc2_b, bn2_g, bn2_b, fc3_w, fc3_b, bn3_g, bn3_b,
        out_w, out_b, out);
}